// round 7
// baseline (speedup 1.0000x reference)
#include <cuda_runtime.h>

#define X 256
#define Y 256
#define Z 192
#define YX (X*Y)
#define NB 2
#define TX 64          // output tile width (elements)
#define TY 16          // output tile height
#define CW 34          // float2 columns = (TX+4)/2
#define CH 20          // rows = TY+4 (halo 2 each side)
#define NTH (CW*CH)    // 680 threads
#define ZCHUNKS 4
#define ZCK (Z/ZCHUNKS) /* 48 */

__device__ __forceinline__ float min3(float a, float b, float c) { return fminf(a, fminf(b, c)); }
__device__ __forceinline__ float max3(float a, float b, float c) { return fmaxf(a, fmaxf(b, c)); }

// out = relu(img - dilate3x3x3(erode3x3x3(img))), stride 1, pad 1.
// erode = min-pool (pad +inf), dilate = max-pool (pad -inf via domain mask).
// Same geometry as the 90.6us float2 kernel (512 blocks, 680 thr, 2/SM), but
// z advances TWO planes per iteration: both planes' float2 values are packed
// into one float4 smem exchange, halving barriers and smem instructions per
// plane while keeping bytes/voxel and block-level concurrency identical.
__global__ __launch_bounds__(NTH, 2)
void soft_skel_kernel(const float* __restrict__ img, float* __restrict__ out) {
    __shared__ float4 sA[CH * CW];
    __shared__ float4 sB[CH * CW];

    const int tid = threadIdx.x;
    const int cx  = tid % CW;            // float2 column index
    const int iy  = tid / CW;            // row index (with halo)
    const int bx0 = blockIdx.x * TX;
    const int by0 = blockIdx.y * TY;
    const int bz  = blockIdx.z;
    const int b   = bz / ZCHUNKS;
    const int z0  = (bz % ZCHUNKS) * ZCK;
    const int z1  = z0 + ZCK;

    const int gx = bx0 + cx * 2 - 2;
    const int gy = by0 + iy - 2;
    const bool inImg = (gx >= 0) && (gx < X) && (gy >= 0) && (gy < Y);
    const bool outP  = (iy >= 2) && (iy <= CH - 3) && (cx >= 1) && (cx <= CW - 2);

    // loop-invariant smem offsets (edge clamps leave garbage only in the
    // outermost shell, which interior outputs never consume)
    const int xl = (cx == 0)      ? 0      : cx - 1;
    const int xr = (cx == CW - 1) ? CW - 1 : cx + 1;
    const int yu = (iy == 0)      ? 0      : iy - 1;
    const int yd = (iy == CH - 1) ? CH - 1 : iy + 1;
    const int offC = iy * CW + cx;
    const int offL = iy * CW + xl;
    const int offR = iy * CW + xr;
    const int offU = yu * CW + cx;
    const int offD = yd * CW + cx;

    const float PINF = __int_as_float(0x7f800000);
    const float NINF = __int_as_float(0xff800000);
    const float2 PI2 = make_float2(PINF, PINF);

    const long base = (long)b * Z * YX + (long)gy * X + gx;
    float* pO = out + base + (long)z0 * YX;

    // img ring v0..v3; e ring: e0 = erode(zc-2), e1 = erode(zc-1)
    float2 v0, v1, v2, v3, e0, e1;

    // load img plane z (masked); z always < Z where called
    #define LOADP(dst, zz) do { \
        const int _z = (zz); \
        (dst) = (inImg && _z >= 0 && _z < Z) \
            ? *(const float2*)(img + base + (long)_z * YX) : PI2; } while (0)

    LOADP(v0, z0 - 2);
    LOADP(v1, z0 - 1);
    LOADP(v2, z0);
    LOADP(v3, z0 + 1);

    // ---------- prologue: erode planes (z0-1, z0) -> e0, e1 (2 barriers)
    {
        float2 p1, p2;
        LOADP(p1, z0 + 2);
        LOADP(p2, z0 + 3);

        float2 zmA, zmB;
        zmA.x = min3(v0.x, v1.x, v2.x); zmA.y = min3(v0.y, v1.y, v2.y);
        zmB.x = min3(v1.x, v2.x, v3.x); zmB.y = min3(v1.y, v2.y, v3.y);
        sA[offC] = make_float4(zmA.x, zmA.y, zmB.x, zmB.y);
        __syncthreads();
        float4 u = sA[offU], d = sA[offD];
        float4 yy;
        yy.x = min3(zmA.x, u.x, d.x); yy.y = min3(zmA.y, u.y, d.y);
        yy.z = min3(zmB.x, u.z, d.z); yy.w = min3(zmB.y, u.w, d.w);
        sB[offC] = yy;
        __syncthreads();
        float4 L = sB[offL], R = sB[offR];
        const bool okA = inImg && ((unsigned)(z0 - 1) < (unsigned)Z);
        const bool okB = inImg;                      // plane z0 always in-domain
        e0.x = okA ? min3(L.y, yy.x, yy.y) : NINF;
        e0.y = okA ? min3(yy.x, yy.y, R.x) : NINF;
        e1.x = okB ? min3(L.w, yy.z, yy.w) : NINF;
        e1.y = okB ? min3(yy.z, yy.w, R.z) : NINF;

        // shift ring by 2 -> v0..v3 = img(z0 .. z0+3)
        v0 = v2; v1 = v3; v2 = p1; v3 = p2;
    }

    // ---------- main loop: each iteration emits output planes zi-1, zi
    for (int zi = z0 + 1; zi < z1; zi += 2) {
        // prefetch planes zi+3, zi+4 for the next iteration
        float2 p1, p2;
        LOADP(p1, zi + 3);
        LOADP(p2, zi + 4);

        // erode-z for planes zi (A) and zi+1 (B); ring = img(zi-1 .. zi+2)
        float2 zmA, zmB;
        zmA.x = min3(v0.x, v1.x, v2.x); zmA.y = min3(v0.y, v1.y, v2.y);
        zmB.x = min3(v1.x, v2.x, v3.x); zmB.y = min3(v1.y, v2.y, v3.y);

        sA[offC] = make_float4(zmA.x, zmA.y, zmB.x, zmB.y);
        __syncthreads();
        float4 u = sA[offU], d = sA[offD];
        float4 yy;
        yy.x = min3(zmA.x, u.x, d.x); yy.y = min3(zmA.y, u.y, d.y);
        yy.z = min3(zmB.x, u.z, d.z); yy.w = min3(zmB.y, u.w, d.w);
        sB[offC] = yy;
        __syncthreads();
        float4 L = sB[offL], R = sB[offR];

        const bool okA = inImg;                               // zi in (z0, z1)
        const bool okB = inImg && ((unsigned)(zi + 1) < (unsigned)Z);
        float2 enA, enB;
        enA.x = okA ? min3(L.y, yy.x, yy.y) : NINF;
        enA.y = okA ? min3(yy.x, yy.y, R.x) : NINF;
        enB.x = okB ? min3(L.w, yy.z, yy.w) : NINF;
        enB.y = okB ? min3(yy.z, yy.w, R.z) : NINF;

        // dilate-z: outputs zi-1 (A) and zi (B)
        float2 dA, dB;
        dA.x = max3(e0.x, e1.x, enA.x); dA.y = max3(e0.y, e1.y, enA.y);
        dB.x = max3(e1.x, enA.x, enB.x); dB.y = max3(e1.y, enA.y, enB.y);
        e0 = enA; e1 = enB;

        sA[offC] = make_float4(dA.x, dA.y, dB.x, dB.y);
        __syncthreads();
        u = sA[offU]; d = sA[offD];
        float4 mm;
        mm.x = max3(dA.x, u.x, d.x); mm.y = max3(dA.y, u.y, d.y);
        mm.z = max3(dB.x, u.z, d.z); mm.w = max3(dB.y, u.w, d.w);
        sB[offC] = mm;
        __syncthreads();
        L = sB[offL]; R = sB[offR];

        if (outP) {
            float2 rA, rB;
            rA.x = fmaxf(v0.x - max3(L.y, mm.x, mm.y), 0.0f);  // v0 = img(zi-1)
            rA.y = fmaxf(v0.y - max3(mm.x, mm.y, R.x), 0.0f);
            rB.x = fmaxf(v1.x - max3(L.w, mm.z, mm.w), 0.0f);  // v1 = img(zi)
            rB.y = fmaxf(v1.y - max3(mm.z, mm.w, R.z), 0.0f);
            *(float2*)pO          = rA;
            *(float2*)(pO + YX)   = rB;
        }
        pO += 2 * YX;

        // shift ring by 2
        v0 = v2; v1 = v3; v2 = p1; v3 = p2;
    }
    #undef LOADP
}

extern "C" void kernel_launch(void* const* d_in, const int* in_sizes, int n_in,
                              void* d_out, int out_size) {
    (void)in_sizes; (void)n_in; (void)out_size;
    const float* img = (const float*)d_in[0];
    float* out = (float*)d_out;
    dim3 grid(X / TX, Y / TY, NB * ZCHUNKS);
    soft_skel_kernel<<<grid, NTH>>>(img, out);
}

// round 8
// speedup vs baseline: 1.0345x; 1.0345x over previous
#include <cuda_runtime.h>

#define X 256
#define Y 256
#define Z 192
#define YX (X*Y)
#define NB 2
#define TX 128          // output tile width (32 quads)
#define TY 16           // output tile height
#define CW 34           // quad columns: 32 output + 1 halo each side
#define CH 20           // rows: 16 + 2 halo each side
#define NTH (CW*CH)     // 680 threads
#define ZCHUNKS 8
#define ZCK (Z/ZCHUNKS) /* 24 */

__device__ __forceinline__ float min3(float a, float b, float c) { return fminf(a, fminf(b, c)); }
__device__ __forceinline__ float max3(float a, float b, float c) { return fmaxf(a, fmaxf(b, c)); }

// out = relu(img - dilate3x3x3(erode3x3x3(img))), stride 1, pad 1.
// erode = min-pool (pad +inf), dilate = max-pool (pad -inf via domain mask).
// Thread owns a float4 x-quad. Separability order z -> x -> y for erode:
// z via register ring, x in REGISTERS (quad + 2 gmem edge scalars), so the
// only erode smem exchange is the y-window. Dilate: z in registers, then one
// smem round giving y-window (float2 U/D) and x-neighbor scalars (stride-1
// float mirror arrays). All smem ops are 32/64-bit (128-bit LDS/STS measured
// ~2x wavefront cost on sm_103a). 2 barriers/plane, ~32 smem B/voxel.
__global__ __launch_bounds__(NTH, 2)
void soft_skel_kernel(const float* __restrict__ img, float* __restrict__ out) {
    __shared__ float2 sE0[NTH], sE1[NTH];   // erode y-exchange: (ax0,ax1),(ax2,ax3)
    __shared__ float2 sD0[NTH], sD1[NTH];   // dilate y-exchange: (d0,d1),(d2,d3)
    __shared__ float  sDL[NTH], sDR[NTH];   // d3 / d0 mirrors for x-neighbors

    const int tid = threadIdx.x;
    const int c   = tid % CW;               // quad column
    const int iy  = tid / CW;               // row (with halo)
    const int bx0 = blockIdx.x * TX;
    const int by0 = blockIdx.y * TY;
    const int bz  = blockIdx.z;
    const int b   = bz / ZCHUNKS;
    const int z0  = (bz % ZCHUNKS) * ZCK;
    const int z1  = z0 + ZCK;

    const int gx = bx0 + (c - 1) * 4;       // first x of the quad
    const int gy = by0 + iy - 2;

    const bool rowV = (gy >= 0) && (gy < Y);
    const bool qIn  = rowV && (gx >= 0) && (gx < X);   // quad uniformly in/out
    const bool lIn  = rowV && (gx - 1 >= 0) && (gx - 1 < X);
    const bool rIn  = rowV && (gx + 4 >= 0) && (gx + 4 < X);
    const bool outP = (c >= 1) && (c <= CW - 2) && (iy >= 2) && (iy <= CH - 3);

    // loop-invariant smem offsets (row clamps leave garbage only where the
    // output chain never looks: rows 0/19 and columns 0/33)
    const int yu = (iy == 0)      ? 0      : iy - 1;
    const int yd = (iy == CH - 1) ? CH - 1 : iy + 1;
    const int cL = (c == 0)       ? 0      : c - 1;
    const int cR = (c == CW - 1)  ? CW - 1 : c + 1;
    const int offC = iy * CW + c;
    const int offU = yu * CW + c;
    const int offD = yd * CW + c;
    const int mLU = yu * CW + cL, mLC = iy * CW + cL, mLD = yd * CW + cL;
    const int mRU = yu * CW + cR, mRC = iy * CW + cR, mRD = yd * CW + cR;

    const float  PINF = __int_as_float(0x7f800000);
    const float  NINF = __int_as_float(0xff800000);
    const float4 PI4  = make_float4(PINF, PINF, PINF, PINF);

    const long base = (long)b * Z * YX + (long)gy * X + gx;
    const float* pIn = img + base;          // + z*YX per plane
    float*       pO  = out + base + (long)z0 * YX;

    // rings: v = raw img quads, l/r = raw edge scalars, er = eroded planes
    float4 v0 = PI4, v1 = PI4, v2;
    float  l0 = PINF, l1 = PINF, l2, r0 = PINF, r1 = PINF, r2;
    float4 er0 = make_float4(NINF, NINF, NINF, NINF), er1 = er0;

    {   // preload plane z0-2
        const int zp = z0 - 2;
        const bool zok = (zp >= 0);
        const long o = (long)zp * YX;
        v2 = (qIn && zok) ? *(const float4*)(pIn + o) : PI4;
        l2 = (lIn && zok) ? pIn[o - 1] : PINF;
        r2 = (rIn && zok) ? pIn[o + 4] : PINF;
    }

    for (int zi = z0 - 2; zi <= z1 + 1; ++zi) {
        // ---- prefetch plane zi+1 (overlaps this plane's compute)
        float4 vn = PI4; float ln = PINF, rn = PINF;
        {
            const int zn = zi + 1;
            if ((unsigned)zn < (unsigned)Z) {
                const long o = (long)zn * YX;
                if (qIn) vn = *(const float4*)(pIn + o);
                if (lIn) ln = pIn[o - 1];
                if (rIn) rn = pIn[o + 4];
            }
        }

        // ---- erode: z-window (registers) at plane zc = zi-1
        float zm0 = min3(v0.x, v1.x, v2.x);
        float zm1 = min3(v0.y, v1.y, v2.y);
        float zm2 = min3(v0.z, v1.z, v2.z);
        float zm3 = min3(v0.w, v1.w, v2.w);
        float zl  = min3(l0, l1, l2);
        float zr  = min3(r0, r1, r2);

        // ---- erode: x-window (registers)
        float ax0 = min3(zl,  zm0, zm1);
        float ax1 = min3(zm0, zm1, zm2);
        float ax2 = min3(zm1, zm2, zm3);
        float ax3 = min3(zm2, zm3, zr);

        // ---- erode: y-window via smem
        sE0[offC] = make_float2(ax0, ax1);
        sE1[offC] = make_float2(ax2, ax3);
        __syncthreads();
        float2 u0 = sE0[offU], d0 = sE0[offD];
        float2 u1 = sE1[offU], d1 = sE1[offD];

        const int  zc = zi - 1;
        const bool ok = qIn && ((unsigned)zc < (unsigned)Z);
        float4 en;
        en.x = ok ? min3(ax0, u0.x, d0.x) : NINF;
        en.y = ok ? min3(ax1, u0.y, d0.y) : NINF;
        en.z = ok ? min3(ax2, u1.x, d1.x) : NINF;
        en.w = ok ? min3(ax3, u1.y, d1.y) : NINF;

        // ---- dilate: z-window (registers) at plane zo = zi-2
        float dd0 = max3(er0.x, er1.x, en.x);
        float dd1 = max3(er0.y, er1.y, en.y);
        float dd2 = max3(er0.z, er1.z, en.z);
        float dd3 = max3(er0.w, er1.w, en.w);
        er0 = er1; er1 = en;

        // ---- dilate: y-window + x-neighbor scalars via smem
        sD0[offC] = make_float2(dd0, dd1);
        sD1[offC] = make_float2(dd2, dd3);
        sDL[offC] = dd3;
        sDR[offC] = dd0;
        __syncthreads();

        if (zi >= z0 + 2) {
            if (outP) {
                float2 a0 = sD0[offU], b0 = sD0[offD];
                float2 a1 = sD1[offU], b1 = sD1[offD];
                float m0 = max3(dd0, a0.x, b0.x);
                float m1 = max3(dd1, a0.y, b0.y);
                float m2 = max3(dd2, a1.x, b1.x);
                float m3 = max3(dd3, a1.y, b1.y);
                float lm = max3(sDL[mLU], sDL[mLC], sDL[mLD]);  // m at x-1
                float rm = max3(sDR[mRU], sDR[mRC], sDR[mRD]);  // m at x+4
                float4 r;
                r.x = fmaxf(v0.x - max3(lm, m0, m1), 0.0f);     // v0 = img(zo)
                r.y = fmaxf(v0.y - max3(m0, m1, m2), 0.0f);
                r.z = fmaxf(v0.z - max3(m1, m2, m3), 0.0f);
                r.w = fmaxf(v0.w - max3(m2, m3, rm), 0.0f);
                *(float4*)pO = r;
            }
            pO += YX;
        }

        // ---- shift rings
        v0 = v1; v1 = v2; v2 = vn;
        l0 = l1; l1 = l2; l2 = ln;
        r0 = r1; r1 = r2; r2 = rn;
    }
}

extern "C" void kernel_launch(void* const* d_in, const int* in_sizes, int n_in,
                              void* d_out, int out_size) {
    (void)in_sizes; (void)n_in; (void)out_size;
    const float* img = (const float*)d_in[0];
    float* out = (float*)d_out;
    dim3 grid(X / TX, Y / TY, NB * ZCHUNKS);
    soft_skel_kernel<<<grid, NTH>>>(img, out);
}

// round 9
// speedup vs baseline: 1.7598x; 1.7012x over previous
#include <cuda_runtime.h>

#define X 256
#define Y 256
#define Z 192
#define YX (X*Y)
#define NB 2
#define TX 64          // output tile width (elements)
#define TY 16          // output tile height
#define CW 34          // float2 columns = (TX+4)/2
#define CH 20          // rows = TY+4 (halo 2 each side)
#define NTH (CW*CH)    // 680 threads
#define ZCHUNKS 8
#define ZCK (Z/ZCHUNKS) /* 24 */

__device__ __forceinline__ float2 fmin2(float2 a, float2 b) {
    return make_float2(fminf(a.x, b.x), fminf(a.y, b.y));
}
__device__ __forceinline__ float2 fmax2(float2 a, float2 b) {
    return make_float2(fmaxf(a.x, b.x), fmaxf(a.y, b.y));
}

// out = relu(img - dilate3x3x3(erode3x3x3(img))), stride 1, pad 1.
// erode = min-pool (pad +inf), dilate = max-pool (pad -inf via domain mask).
// EXACT dataflow of the 90.6us champion (float2 column per thread, register
// z-rings, 4 LDS.64 exchange rounds/plane). Only change: 3 blocks/SM
// (launch_bounds cap -> ~32 regs, 2040 threads/SM) for +50% warp-level
// latency hiding, and shorter z-chunks (ZCK=24) so the 1024-block grid
// load-balances across the 444 block slots.
__global__ __launch_bounds__(NTH, 3)
void soft_skel_kernel(const float* __restrict__ img, float* __restrict__ out) {
    __shared__ float2 sA[CH * CW];
    __shared__ float2 sB[CH * CW];

    const int tid = threadIdx.x;
    const int cx  = tid % CW;            // float2 column index
    const int iy  = tid / CW;            // row index (with halo)
    const int bx0 = blockIdx.x * TX;
    const int by0 = blockIdx.y * TY;
    const int bz  = blockIdx.z;
    const int b   = bz / ZCHUNKS;
    const int z0  = (bz % ZCHUNKS) * ZCK;
    const int z1  = z0 + ZCK;

    const int gx = bx0 + cx * 2 - 2;     // first element of the pair (even)
    const int gy = by0 + iy - 2;

    // pair is always fully inside or fully outside in x (gx even, X even)
    const bool inImg = (gx >= 0) && (gx < X) && (gy >= 0) && (gy < Y);
    const bool outP  = (iy >= 2) && (iy <= CH - 3) && (cx >= 1) && (cx <= CW - 2);

    // loop-invariant shared offsets (clamped at edges; clamp garbage stays in
    // the outermost shell, never consumed by interior outputs)
    const int xl = (cx == 0)      ? 0      : cx - 1;
    const int xr = (cx == CW - 1) ? CW - 1 : cx + 1;
    const int yu = (iy == 0)      ? 0      : iy - 1;
    const int yd = (iy == CH - 1) ? CH - 1 : iy + 1;
    const int offC = iy * CW + cx;
    const int offL = iy * CW + xl;
    const int offR = iy * CW + xr;
    const int offU = yu * CW + cx;
    const int offD = yd * CW + cx;

    const float  PINF = __int_as_float(0x7f800000);
    const float  NINF = __int_as_float(0xff800000);
    const float2 PI2  = make_float2(PINF, PINF);

    const long base = (long)b * Z * YX + (long)gy * X + gx;
    const float* pIn = img + base + (long)(z0 - 1) * YX;   // next plane to load
    float*       pO  = out + base + (long)z0 * YX;

    // img ring: v0 = plane zi-2, v1 = zi-1, v2 = zi
    float2 v0 = PI2, v1 = PI2, v2;
    // erode ring: e0 = e(zi-3), e1 = e(zi-2)
    float2 e0 = make_float2(NINF, NINF), e1 = e0;

    // preload plane z0-2
    v2 = (inImg && (z0 - 2) >= 0) ? *(const float2*)(pIn - YX) : PI2;

    for (int zi = z0 - 2; zi <= z1 + 1; ++zi) {
        // ---- prefetch plane zi+1 (issued 4 barrier-phases before use)
        float2 vn = PI2;
        {
            const int zn = zi + 1;
            if (inImg && (unsigned)zn < (unsigned)Z)
                vn = *(const float2*)pIn;
            pIn += YX;
        }

        // ---- erode-z at plane zc = zi-1 (registers)
        float2 zm = fmin2(v0, fmin2(v1, v2));

        // ---- erode-y via smem (buffer A)
        sA[offC] = zm;
        __syncthreads();
        float2 yb = fmin2(sA[offU], fmin2(zm, sA[offD]));
        sB[offC] = yb;
        __syncthreads();

        // ---- erode-x (buffer B) + domain mask (-inf outside for dilate pad)
        {
            float2 L = sB[offL];
            float2 R = sB[offR];
            float ex = fminf(L.y, fminf(yb.x, yb.y));
            float ey = fminf(yb.x, fminf(yb.y, R.x));
            const int  zc = zi - 1;
            const bool vC = inImg && ((unsigned)zc < (unsigned)Z);
            float2 en;
            en.x = vC ? ex : NINF;
            en.y = vC ? ey : NINF;

            // ---- dilate-z at plane zo = zi-2 (registers)
            float2 dd = fmax2(e0, fmax2(e1, en));
            e0 = e1; e1 = en;

            // ---- dilate-y via smem (buffer A reusable after sync above)
            sA[offC] = dd;
            __syncthreads();
            float2 m = fmax2(sA[offU], fmax2(dd, sA[offD]));
            sB[offC] = m;
            __syncthreads();

            // ---- dilate-x + output: opened at plane zo = zi-2
            if (zi >= z0 + 2) {
                if (outP) {
                    float2 Lm = sB[offL];
                    float2 Rm = sB[offR];
                    float ox = fmaxf(Lm.y, fmaxf(m.x, m.y));
                    float oy = fmaxf(m.x, fmaxf(m.y, Rm.x));
                    float2 r;
                    r.x = fmaxf(v0.x - ox, 0.0f);   // v0 = img at plane zo
                    r.y = fmaxf(v0.y - oy, 0.0f);
                    *(float2*)pO = r;
                }
                pO += YX;
            }
        }

        // ---- shift img ring
        v0 = v1; v1 = v2; v2 = vn;
    }
}

extern "C" void kernel_launch(void* const* d_in, const int* in_sizes, int n_in,
                              void* d_out, int out_size) {
    (void)in_sizes; (void)n_in; (void)out_size;
    const float* img = (const float*)d_in[0];
    float* out = (float*)d_out;
    dim3 grid(X / TX, Y / TY, NB * ZCHUNKS);
    soft_skel_kernel<<<grid, NTH>>>(img, out);
}

// round 10
// speedup vs baseline: 1.8814x; 1.0691x over previous
#include <cuda_runtime.h>

#define X 256
#define Y 256
#define Z 192
#define YX (X*Y)
#define NB 2
#define TX 64          // output tile width (elements)
#define TY 32          // output tile height
#define CW 34          // float2 columns = (TX+4)/2
#define CH 36          // rows = TY+4 (halo 2 each side)
#define TR 18          // thread-rows: each thread owns 2 adjacent rows
#define NTH (CW*TR)    // 612 threads
#define ZCHUNKS 8
#define ZCK (Z/ZCHUNKS) /* 24 */

__device__ __forceinline__ float2 fmin2(float2 a, float2 b) {
    return make_float2(fminf(a.x, b.x), fminf(a.y, b.y));
}
__device__ __forceinline__ float2 fmax2(float2 a, float2 b) {
    return make_float2(fmaxf(a.x, b.x), fmaxf(a.y, b.y));
}
__device__ __forceinline__ float2 fmin3_2(float2 a, float2 b, float2 c) {
    return fmin2(a, fmin2(b, c));
}
__device__ __forceinline__ float2 fmax3_2(float2 a, float2 b, float2 c) {
    return fmax2(a, fmax2(b, c));
}

// out = relu(img - dilate3x3x3(erode3x3x3(img))), stride 1, pad 1.
// erode = min-pool (pad +inf), dilate = max-pool (pad -inf via domain mask).
// Same 4-round LDS.64 ping-pong structure as the 90.6us champion, but each
// thread owns TWO adjacent y-rows of its float2 column: the y-window needs
// only ONE neighbor row from above and below per pair, so smem ops per output
// voxel drop 25%, barrier cost per voxel halves, and y-halo redundancy falls
// from 1.33x to 1.20x. All smem ops remain uniform 64-bit.
__global__ __launch_bounds__(NTH, 2)
void soft_skel_kernel(const float* __restrict__ img, float* __restrict__ out) {
    __shared__ float2 sA[CH * CW];
    __shared__ float2 sB[CH * CW];

    const int tid = threadIdx.x;
    const int cx  = tid % CW;            // float2 column index
    const int ry  = tid / CW;            // thread-row (owns rows 2ry, 2ry+1)
    const int iy0 = 2 * ry;
    const int iy1 = iy0 + 1;
    const int bx0 = blockIdx.x * TX;
    const int by0 = blockIdx.y * TY;
    const int bz  = blockIdx.z;
    const int b   = bz / ZCHUNKS;
    const int z0  = (bz % ZCHUNKS) * ZCK;
    const int z1  = z0 + ZCK;

    const int gx  = bx0 + cx * 2 - 2;    // first element of the pair (even)
    const int gy0 = by0 + iy0 - 2;
    const int gy1 = gy0 + 1;

    const bool inX   = (gx >= 0) && (gx < X);   // pair uniformly in/out in x
    const bool in0   = inX && (gy0 >= 0) && (gy0 < Y);
    const bool in1   = inX && (gy1 >= 0) && (gy1 < Y);
    // outputs: rows 2..33 <=> ry in [1,16]; cols 1..32
    const bool outP  = (ry >= 1) && (ry <= TR - 2) && (cx >= 1) && (cx <= CW - 2);

    // loop-invariant smem offsets (clamps leave garbage only in the outer
    // shell rows 0/35 and cols 0/33, which interior outputs never consume)
    const int xl = (cx == 0)      ? 0      : cx - 1;
    const int xr = (cx == CW - 1) ? CW - 1 : cx + 1;
    const int yu = (ry == 0)      ? 0      : iy0 - 1;
    const int yd = (ry == TR - 1) ? CH - 1 : iy1 + 1;
    const int off0  = iy0 * CW + cx;     // own row 0
    const int off1  = iy1 * CW + cx;     // own row 1
    const int offU  = yu  * CW + cx;     // row above the pair
    const int offD  = yd  * CW + cx;     // row below the pair
    const int off0L = iy0 * CW + xl, off0R = iy0 * CW + xr;
    const int off1L = iy1 * CW + xl, off1R = iy1 * CW + xr;

    const float  PINF = __int_as_float(0x7f800000);
    const float  NINF = __int_as_float(0xff800000);
    const float2 PI2  = make_float2(PINF, PINF);
    const float2 NI2  = make_float2(NINF, NINF);

    const long base = (long)b * Z * YX + (long)gy0 * X + gx;
    const float* pIn = img + base + (long)(z0 - 1) * YX;   // next plane to load
    float*       pO  = out + base + (long)z0 * YX;

    // img rings per row: a* = row iy0, b* = row iy1 (planes zi-2, zi-1, zi)
    float2 a0 = PI2, a1 = PI2, a2;
    float2 b0 = PI2, b1 = PI2, b2;
    // erode rings per row: e(zi-3), e(zi-2)
    float2 ea0 = NI2, ea1 = NI2;
    float2 eb0 = NI2, eb1 = NI2;

    {   // preload plane z0-2
        const bool zok = (z0 - 2) >= 0;
        a2 = (in0 && zok) ? *(const float2*)(pIn - YX)     : PI2;
        b2 = (in1 && zok) ? *(const float2*)(pIn - YX + X) : PI2;
    }

    for (int zi = z0 - 2; zi <= z1 + 1; ++zi) {
        // ---- prefetch plane zi+1 (issued 4 barrier-phases before use)
        float2 an = PI2, bn = PI2;
        {
            const int zn = zi + 1;
            const bool zok = (unsigned)zn < (unsigned)Z;
            if (in0 && zok) an = *(const float2*)pIn;
            if (in1 && zok) bn = *(const float2*)(pIn + X);
            pIn += YX;
        }

        // ---- erode-z at plane zc = zi-1 (registers, both rows)
        float2 zmA = fmin3_2(a0, a1, a2);
        float2 zmB = fmin3_2(b0, b1, b2);

        // ---- erode-y via smem (buffer A): pair needs only 1 up + 1 down
        sA[off0] = zmA;
        sA[off1] = zmB;
        __syncthreads();
        float2 up = sA[offU];
        float2 dn = sA[offD];
        float2 ybA = fmin3_2(up,  zmA, zmB);
        float2 ybB = fmin3_2(zmA, zmB, dn);

        sB[off0] = ybA;
        sB[off1] = ybB;
        __syncthreads();

        // ---- erode-x (buffer B) + domain mask (-inf outside for dilate pad)
        {
            float2 LA = sB[off0L], RA = sB[off0R];
            float2 LB = sB[off1L], RB = sB[off1R];
            const int  zc  = zi - 1;
            const bool zin = (unsigned)zc < (unsigned)Z;
            const bool v0v = in0 && zin;
            const bool v1v = in1 && zin;
            float2 enA, enB;
            enA.x = v0v ? fminf(LA.y, fminf(ybA.x, ybA.y)) : NINF;
            enA.y = v0v ? fminf(ybA.x, fminf(ybA.y, RA.x)) : NINF;
            enB.x = v1v ? fminf(LB.y, fminf(ybB.x, ybB.y)) : NINF;
            enB.y = v1v ? fminf(ybB.x, fminf(ybB.y, RB.x)) : NINF;

            // ---- dilate-z at plane zo = zi-2 (registers)
            float2 dA = fmax3_2(ea0, ea1, enA);
            float2 dB = fmax3_2(eb0, eb1, enB);
            ea0 = ea1; ea1 = enA;
            eb0 = eb1; eb1 = enB;

            // ---- dilate-y via smem (buffer A reusable after sync above)
            sA[off0] = dA;
            sA[off1] = dB;
            __syncthreads();
            float2 upd = sA[offU];
            float2 dnd = sA[offD];
            float2 mA = fmax3_2(upd, dA, dB);
            float2 mB = fmax3_2(dA,  dB, dnd);
            sB[off0] = mA;
            sB[off1] = mB;
            __syncthreads();

            // ---- dilate-x + output: opened at plane zo = zi-2
            if (zi >= z0 + 2) {
                if (outP) {
                    float2 LmA = sB[off0L], RmA = sB[off0R];
                    float2 LmB = sB[off1L], RmB = sB[off1R];
                    float2 r0, r1;
                    r0.x = fmaxf(a0.x - fmaxf(LmA.y, fmaxf(mA.x, mA.y)), 0.0f);
                    r0.y = fmaxf(a0.y - fmaxf(mA.x, fmaxf(mA.y, RmA.x)), 0.0f);
                    r1.x = fmaxf(b0.x - fmaxf(LmB.y, fmaxf(mB.x, mB.y)), 0.0f);
                    r1.y = fmaxf(b0.y - fmaxf(mB.x, fmaxf(mB.y, RmB.x)), 0.0f);
                    *(float2*)pO       = r0;   // a0/b0 = img at plane zo
                    *(float2*)(pO + X) = r1;
                }
                pO += YX;
            }
        }

        // ---- shift img rings
        a0 = a1; a1 = a2; a2 = an;
        b0 = b1; b1 = b2; b2 = bn;
    }
}

extern "C" void kernel_launch(void* const* d_in, const int* in_sizes, int n_in,
                              void* d_out, int out_size) {
    (void)in_sizes; (void)n_in; (void)out_size;
    const float* img = (const float*)d_in[0];
    float* out = (float*)d_out;
    dim3 grid(X / TX, Y / TY, NB * ZCHUNKS);
    soft_skel_kernel<<<grid, NTH>>>(img, out);
}